// round 10
// baseline (speedup 1.0000x reference)
#include <cuda_runtime.h>

// Problem constants
#define B_DIM 8
#define D_DIM 40
#define H_DIM 32
#define W_DIM 88
#define C_DIM 80
#define QUADS (C_DIM / 4)
#define NX 256
#define NY 256
#define NCELL (NX * NY)                      // 65536 cells per batch
#define NPTS (B_DIM * D_DIM * H_DIM * W_DIM) // 901120 points
#define NROWS (B_DIM * D_DIM * H_DIM)        // 10240 rows of 88
// NZ = 1

#define NOT_FIRST_BIT (1 << 16)

// Scratch accumulator (cell-major): (B, NCELL, C) fp32 = 168 MB. .bss zero.
__device__ float g_scratch[(long long)B_DIM * NCELL * C_DIM];
// Per-(b,cell) contributor count: 524288 ints = 2 MB.
__device__ int g_count[B_DIM * NCELL];
// Packed per-point: bits[0:16] = flat cell, bit16 = "not rank-0", -1 = OOB.
__device__ int g_flat[NPTS];

// ---------------------------------------------------------------------------
// Reset the count table: 524288 ints = 131072 int4 -> 512 blocks x 256 thr.
// (Round-9 bug: grid covered only 1/4 of the table -> replay accumulation.)
// ---------------------------------------------------------------------------
__global__ void __launch_bounds__(256) zero_count_kernel() {
    int4* const ct = (int4*)g_count;
    const int i = blockIdx.x * 256 + threadIdx.x;   // 0 .. 131071 (exact grid)
    ct[i] = make_int4(0, 0, 0, 0);
}

// ---------------------------------------------------------------------------
// Count pass: one thread per point. Computes the cell index, takes a per-cell
// rank via atomicAdd-return, caches (flat | rank0-bit) into g_flat.
// ---------------------------------------------------------------------------
__global__ void __launch_bounds__(256) count_kernel(
    const float* __restrict__ geom)   // (B, D, H, W, 3)
{
    const int n = blockIdx.x * 256 + threadIdx.x;   // 0 .. NPTS-1 (exact grid)
    const float* g = geom + (long long)n * 3;
    const float gx = g[0];
    const float gy = g[1];
    const float gz = g[2];

    int packed = -1;
    if (gx >= -51.2f && gx < 51.2f &&
        gy >= -51.2f && gy < 51.2f &&
        gz >= -10.0f && gz < 10.0f) {
        // Match XLA: div-by-const lowered to mul-by-reciprocal (1/0.4 == 2.5f
        // exactly in fp32). add-then-mul cannot be FMA-contracted.
        const float rx = (gx + 51.2f) * 2.5f;
        const float ry = (gy + 51.2f) * 2.5f;
        int ix = (int)rx;
        int iy = (int)ry;
        ix = min(max(ix, 0), NX - 1);
        iy = min(max(iy, 0), NY - 1);
        const int flat = ix * NY + iy;

        const int b = n / (D_DIM * H_DIM * W_DIM);
        const int old = atomicAdd(&g_count[b * NCELL + flat], 1);
        packed = flat | (old == 0 ? 0 : NOT_FIRST_BIT);
    }
    g_flat[n] = packed;
}

// ---------------------------------------------------------------------------
// Scatter pass A (rank-0 points): plain STG.128 per quad — writes the value
// AND initializes the cell (overwriting stale scratch), replacing the zero
// kernel. Kernel boundary orders these stores before pass B's REDs.
// Scatter pass B (rank>=1 points): red.global.add.v4.f32.
// One block per (b, d, h) row; phase 1 caches the row's packed flags.
// ---------------------------------------------------------------------------
template <bool FIRST_PASS>
__global__ void __launch_bounds__(256) scatter_kernel(
    const float* __restrict__ x)      // (B, D, C, H, W)
{
    __shared__ int s_flat[W_DIM];     // flat cell, or -1 if not in this pass

    const int bid = blockIdx.x;           // 0 .. NROWS-1
    const int h   = bid % H_DIM;
    const int bd  = bid / H_DIM;
    const int d   = bd % D_DIM;
    const int b   = bd / D_DIM;

    const int t = threadIdx.x;

    if (t < W_DIM) {
        const int packed = g_flat[bid * W_DIM + t];
        int flat = -1;
        if (packed >= 0) {
            const bool is_first = (packed & NOT_FIRST_BIT) == 0;
            if (is_first == FIRST_PASS) flat = packed & 0xFFFF;
        }
        s_flat[t] = flat;
    }
    __syncthreads();

    // x index: (((b*D+d)*C + c)*H + h)*W + w
    const long long x_base = ((long long)(b * D_DIM + d) * C_DIM * H_DIM + h) * W_DIM;
    const int c_stride = H_DIM * W_DIM;                       // 2816
    float* const sb = g_scratch + (long long)b * NCELL * C_DIM;

    const int total = QUADS * W_DIM;     // 20 * 88 = 1760
    for (int idx = t; idx < total; idx += blockDim.x) {
        const int q = idx / W_DIM;       // channel quad 0..19
        const int w = idx - q * W_DIM;
        const int flat = s_flat[w];
        if (flat >= 0) {
            // Evict-first: x is streamed once — keep L2 for the RMW set.
            const float* xp = x + x_base + (long long)(q * 4) * c_stride + w;
            float v0 = __ldcs(xp);
            float v1 = __ldcs(xp + c_stride);
            float v2 = __ldcs(xp + 2 * c_stride);
            float v3 = __ldcs(xp + 3 * c_stride);
            float* dst = sb + (long long)flat * C_DIM + q * 4;  // 16B aligned
            if (FIRST_PASS) {
                // Rank-0: plain vec store = value + initialization.
                *(float4*)dst = make_float4(v0, v1, v2, v3);
            } else {
                asm volatile("red.global.add.v4.f32 [%0], {%1, %2, %3, %4};"
                             :: "l"(dst), "f"(v0), "f"(v1), "f"(v2), "f"(v3)
                             : "memory");
            }
        }
    }
}

// ---------------------------------------------------------------------------
// Count-aware transpose: scratch (B, NCELL, C) -> out (B, C, NCELL).
// 64 cells x 80 channels per block. count==0 cells are synthesized as zeros
// (no scratch read). Store phase uses conflict-free scalar LDS (lane stride
// 81 == 17 mod 32) + perfectly coalesced STG.32 (32 consecutive cells).
// ---------------------------------------------------------------------------
__global__ void __launch_bounds__(256) transpose_kernel(float* __restrict__ out)
{
    __shared__ float tile[64][81];
    __shared__ int s_cnt[64];

    const int blk   = blockIdx.x;            // 0 .. B*1024-1
    const int b     = blk >> 10;
    const int tile0 = (blk & 1023) * 64;     // first cell of tile
    const int t     = threadIdx.x;

    if (t < 64) s_cnt[t] = __ldg(&g_count[b * NCELL + tile0 + t]);
    __syncthreads();

    const float4* src = (const float4*)(g_scratch +
                        ((long long)b * NCELL + tile0) * C_DIM);

    // Load: 64 cells * 20 float4; skip the global read for empty cells.
    #pragma unroll
    for (int i = t; i < 64 * 20; i += 256) {
        const int cell = i / 20;
        const int q    = i - cell * 20;
        float4 v = make_float4(0.f, 0.f, 0.f, 0.f);
        if (s_cnt[cell] > 0) v = __ldcs(&src[i]);
        tile[cell][q * 4 + 0] = v.x;
        tile[cell][q * 4 + 1] = v.y;
        tile[cell][q * 4 + 2] = v.z;
        tile[cell][q * 4 + 3] = v.w;
    }
    __syncthreads();

    // Store: 80 channels * 64 cells, scalar. Lanes cover 32 consecutive
    // cells of one channel: LDS conflict-free, STG.32 fully coalesced.
    float* ob = out + (long long)b * C_DIM * NCELL + tile0;
    #pragma unroll
    for (int i = t; i < 80 * 64; i += 256) {
        const int c    = i >> 6;       // / 64
        const int cell = i & 63;
        __stcs(ob + (long long)c * NCELL + cell, tile[cell][c]);
    }
}

extern "C" void kernel_launch(void* const* d_in, const int* in_sizes, int n_in,
                              void* d_out, int out_size) {
    const float* geom = (const float*)d_in[0];   // (8,40,32,88,3)
    const float* x    = (const float*)d_in[1];   // (8,40,80,32,88)
    float* out        = (float*)d_out;           // (8,80,256,256)

    // 524288 ints -> 131072 int4 / 256 = 512 blocks exactly.
    zero_count_kernel<<<512, 256>>>();
    // 901120 points / 256 = 3520 blocks exactly.
    count_kernel<<<3520, 256>>>(geom);
    // Pass A: rank-0 stores (doubles as scratch initialization).
    scatter_kernel<true><<<NROWS, 256>>>(x);
    // Pass B: rank>=1 reductions (ordered after pass A by kernel boundary).
    scatter_kernel<false><<<NROWS, 256>>>(x);
    transpose_kernel<<<B_DIM * (NCELL / 64), 256>>>(out);
}

// round 11
// speedup vs baseline: 1.3060x; 1.3060x over previous
#include <cuda_runtime.h>

// Problem constants
#define B_DIM 8
#define D_DIM 40
#define H_DIM 32
#define W_DIM 88
#define C_DIM 80
#define QUADS (C_DIM / 4)
#define NX 256
#define NY 256
#define NCELL (NX * NY)                      // 65536 cells per batch
#define NPTS (B_DIM * D_DIM * H_DIM * W_DIM) // 901120 points
#define NROWS (B_DIM * D_DIM * H_DIM)        // 10240 rows of 88
// NZ = 1

// Scratch accumulator (cell-major): (B, NCELL, C) fp32 = 168 MB. .bss zero.
// Invariant at entry to every kernel_launch call: count table is all-zero and
// every cell that will have count>=2 this call is zero (count==1 cells get
// fully overwritten by the sole-store; count==0 cells are never read).
// Maintained by transpose_zero_kernel at the end of each call.
__device__ float g_scratch[(long long)B_DIM * NCELL * C_DIM];
// Per-(b,cell) contributor count: 524288 ints = 2 MB. .bss zero.
__device__ int g_count[B_DIM * NCELL];
// Cached flat cell index per point (-1 = out of bounds): 3.6 MB.
__device__ int g_flat[NPTS];

// ---------------------------------------------------------------------------
// Count pass: one thread per point. Computes the cell index (cached into
// g_flat) and bumps the per-(b,cell) contributor count.
// ---------------------------------------------------------------------------
__global__ void __launch_bounds__(256) count_kernel(
    const float* __restrict__ geom)   // (B, D, H, W, 3)
{
    const int n = blockIdx.x * 256 + threadIdx.x;   // 0 .. NPTS-1 (exact grid)
    const float* g = geom + (long long)n * 3;
    const float gx = g[0];
    const float gy = g[1];
    const float gz = g[2];

    int flat = -1;
    if (gx >= -51.2f && gx < 51.2f &&
        gy >= -51.2f && gy < 51.2f &&
        gz >= -10.0f && gz < 10.0f) {
        // Match XLA: div-by-const lowered to mul-by-reciprocal (1/0.4 == 2.5f
        // exactly in fp32). add-then-mul cannot be FMA-contracted.
        const float rx = (gx + 51.2f) * 2.5f;
        const float ry = (gy + 51.2f) * 2.5f;
        int ix = (int)rx;
        int iy = (int)ry;
        ix = min(max(ix, 0), NX - 1);
        iy = min(max(iy, 0), NY - 1);
        flat = ix * NY + iy;
    }
    g_flat[n] = flat;
    if (flat >= 0) {
        const int b = n / (D_DIM * H_DIM * W_DIM);
        atomicAdd(&g_count[b * NCELL + flat], 1);   // RED (no return)
    }
}

// ---------------------------------------------------------------------------
// Scatter: one block per (b, d, h) row of W=88 points (single pass — reads x
// exactly once; any point-split re-reads most x sectors, round-10 lesson).
// Phase 1: threads 0..87 load the cached cell index + contributor count.
// Phase 2: loop over (quad q, w): 4 evict-first coalesced x loads; sole
//          contributor -> plain STG.128 (no LTS atomic slot, and doubles as
//          the cell's initialization); otherwise red.global.add.v4.f32 onto
//          the pre-zeroed base.
// ---------------------------------------------------------------------------
__global__ void __launch_bounds__(256) scatter_kernel(
    const float* __restrict__ x)      // (B, D, C, H, W)
{
    __shared__ int s_flat[W_DIM];
    __shared__ int s_cnt[W_DIM];

    const int bid = blockIdx.x;           // 0 .. NROWS-1
    const int h   = bid % H_DIM;
    const int bd  = bid / H_DIM;
    const int d   = bd % D_DIM;
    const int b   = bd / D_DIM;

    const int t = threadIdx.x;

    if (t < W_DIM) {
        const int flat = g_flat[bid * W_DIM + t];
        s_flat[t] = flat;
        s_cnt[t]  = (flat >= 0) ? __ldg(&g_count[b * NCELL + flat]) : 0;
    }
    __syncthreads();

    // x index: (((b*D+d)*C + c)*H + h)*W + w
    const long long x_base = ((long long)(b * D_DIM + d) * C_DIM * H_DIM + h) * W_DIM;
    const int c_stride = H_DIM * W_DIM;                       // 2816
    float* const sb = g_scratch + (long long)b * NCELL * C_DIM;

    const int total = QUADS * W_DIM;     // 20 * 88 = 1760
    for (int idx = t; idx < total; idx += blockDim.x) {
        const int q = idx / W_DIM;       // channel quad 0..19
        const int w = idx - q * W_DIM;
        const int flat = s_flat[w];
        if (flat >= 0) {
            // Evict-first: x is streamed once — keep L2 for the RMW set.
            const float* xp = x + x_base + (long long)(q * 4) * c_stride + w;
            float v0 = __ldcs(xp);
            float v1 = __ldcs(xp + c_stride);
            float v2 = __ldcs(xp + 2 * c_stride);
            float v3 = __ldcs(xp + 3 * c_stride);
            float* dst = sb + (long long)flat * C_DIM + q * 4;  // 16B aligned
            if (s_cnt[w] == 1) {
                // Sole contributor: plain vec store = value + initialization.
                *(float4*)dst = make_float4(v0, v1, v2, v3);
            } else {
                asm volatile("red.global.add.v4.f32 [%0], {%1, %2, %3, %4};"
                             :: "l"(dst), "f"(v0), "f"(v1), "f"(v2), "f"(v3)
                             : "memory");
            }
        }
    }
}

// ---------------------------------------------------------------------------
// Transpose + state restore: scratch (B, NCELL, C) -> out (B, C, NCELL).
// 128 cells x 80 channels per block (10 global loads/thread for MLP).
//  - count==0 cells synthesized as zeros (no scratch read).
//  - Store phase: conflict-free scalar LDS (stride 81 == 17 mod 32) +
//    perfectly coalesced STG.32.
//  - Afterwards (well past the loads — avoids the round-4/5 load-then-store
//    same-address poison): zero the scratch of count>=2 cells and zero the
//    count words, restoring the entry invariant for the next call/replay.
// ---------------------------------------------------------------------------
__global__ void __launch_bounds__(256) transpose_zero_kernel(float* __restrict__ out)
{
    __shared__ float tile[128][81];
    __shared__ int s_cnt[128];

    const int blk   = blockIdx.x;            // 0 .. B*512-1
    const int b     = blk >> 9;
    const int tile0 = (blk & 511) * 128;     // first cell of tile
    const int t     = threadIdx.x;

    if (t < 128) s_cnt[t] = __ldg(&g_count[b * NCELL + tile0 + t]);
    __syncthreads();

    float4* const src = (float4*)(g_scratch +
                        ((long long)b * NCELL + tile0) * C_DIM);

    // Load: 128 cells * 20 float4 = 2560 vec loads (10/thread), coalesced;
    // empty cells synthesized as zero without touching global.
    #pragma unroll
    for (int k = 0; k < 10; k++) {
        const int i    = t + k * 256;
        const int cell = i / 20;
        const int q    = i - cell * 20;
        float4 v = make_float4(0.f, 0.f, 0.f, 0.f);
        if (s_cnt[cell] > 0) v = __ldcs(&src[i]);
        tile[cell][q * 4 + 0] = v.x;
        tile[cell][q * 4 + 1] = v.y;
        tile[cell][q * 4 + 2] = v.z;
        tile[cell][q * 4 + 3] = v.w;
    }
    __syncthreads();

    // Store: 80 channels * 128 cells, scalar (40/thread). Lanes cover 32
    // consecutive cells of one channel: LDS conflict-free, STG.32 coalesced.
    float* ob = out + (long long)b * C_DIM * NCELL + tile0;
    #pragma unroll
    for (int k = 0; k < 40; k++) {
        const int i    = t + k * 256;
        const int c    = i >> 7;       // / 128
        const int cell = i & 127;
        __stcs(ob + (long long)c * NCELL + cell, tile[cell][c]);
    }

    // Restore scratch zeros for cells that needed a zero base this call
    // (count>=2). count==1 cells will be overwritten by next call's sole
    // store; count==0 cells are never read.
    #pragma unroll
    for (int k = 0; k < 10; k++) {
        const int i    = t + k * 256;
        const int cell = i / 20;
        if (s_cnt[cell] >= 2) {
            src[i] = make_float4(0.f, 0.f, 0.f, 0.f);
        }
    }

    // Restore count words to zero (128 ints = 32 int4).
    if (t < 32) {
        ((int4*)(g_count + b * NCELL + tile0))[t] = make_int4(0, 0, 0, 0);
    }
}

extern "C" void kernel_launch(void* const* d_in, const int* in_sizes, int n_in,
                              void* d_out, int out_size) {
    const float* geom = (const float*)d_in[0];   // (8,40,32,88,3)
    const float* x    = (const float*)d_in[1];   // (8,40,80,32,88)
    float* out        = (float*)d_out;           // (8,80,256,256)

    // 901120 points / 256 = 3520 blocks exactly.
    count_kernel<<<3520, 256>>>(geom);
    // Single-pass scatter (x read exactly once).
    scatter_kernel<<<NROWS, 256>>>(x);
    // Transpose + restore zero-state for next call. 8*512 = 4096 blocks.
    transpose_zero_kernel<<<B_DIM * (NCELL / 128), 256>>>(out);
}